// round 15
// baseline (speedup 1.0000x reference)
#include <cuda_runtime.h>

#define NN 40000
#define NE 640000
#define NBATCH 64

typedef unsigned long long ull;

// ---------------- f32x2 helpers ----------------
__device__ __forceinline__ ull pk2(float lo, float hi) {
    ull r; asm("mov.b64 %0, {%1,%2};" : "=l"(r) : "f"(lo), "f"(hi)); return r;
}
__device__ __forceinline__ void upk2(ull v, float& lo, float& hi) {
    asm("mov.b64 {%0,%1}, %2;" : "=f"(lo), "=f"(hi) : "l"(v));
}
__device__ __forceinline__ ull fma2(ull a, ull b, ull c) {
    ull d; asm("fma.rn.f32x2 %0, %1, %2, %3;" : "=l"(d) : "l"(a), "l"(b), "l"(c)); return d;
}
union f4u { float4 f; ull u[2]; };
union f2u { float2 f; ull u; };

// ---------------- cp.async helpers ----------------
__device__ __forceinline__ void cpa16(unsigned s, const void* g) {
    asm volatile("cp.async.cg.shared.global [%0], [%1], 16;" :: "r"(s), "l"(g));
}
#define CPA_COMMIT() asm volatile("cp.async.commit_group;" ::: "memory")
#define CPA_WAIT0()  asm volatile("cp.async.wait_group 0;" ::: "memory")

// ---------------- scratch ----------------
__device__ float g_xl[NN * 128];
__device__ float g_xr[NN * 128];
__device__ float g_h [NN * 128];
__device__ float g_w  [NE * 2];       // exp(logit)
__device__ int   g_rowptr[NN + 1];
__device__ int   g_cursor[NN];
__device__ int   g_eid[NE];
__device__ float g_gate[NN];          // exp(gate logit)

// ---------------- CSR build ----------------
__global__ void k_init() {
    int i = blockIdx.x * blockDim.x + threadIdx.x;
    if (i < NN) g_cursor[i] = 0;
}
__global__ void k_count(const int* __restrict__ dst) {
    int e = blockIdx.x * blockDim.x + threadIdx.x;
    if (e < NE) atomicAdd(&g_cursor[dst[e]], 1);
}
__global__ void __launch_bounds__(1024) k_scan() {
    const int t = threadIdx.x;
    const int lane = t & 31, w = t >> 5;
    const int base = t * 40;
    const int n0 = min(base, NN), n1 = min(base + 40, NN);
    int sum = 0;
    for (int i = n0; i < n1; i++) sum += g_cursor[i];
    int v = sum;
    #pragma unroll
    for (int off = 1; off < 32; off <<= 1) {
        int u = __shfl_up_sync(0xffffffffu, v, off);
        if (lane >= off) v += u;
    }
    __shared__ int ws[32];
    if (lane == 31) ws[w] = v;
    __syncthreads();
    if (w == 0) {
        int x = ws[lane];
        #pragma unroll
        for (int off = 1; off < 32; off <<= 1) {
            int u = __shfl_up_sync(0xffffffffu, x, off);
            if (lane >= off) x += u;
        }
        ws[lane] = x;
    }
    __syncthreads();
    int excl = v - sum + (w > 0 ? ws[w - 1] : 0);
    if (t == 0) g_rowptr[0] = 0;
    int run = excl;
    for (int i = n0; i < n1; i++) {
        int c = g_cursor[i];
        g_cursor[i] = run;
        g_rowptr[i + 1] = run + c;
        run += c;
    }
}
__global__ void k_scatter(const int* __restrict__ dst) {
    int e = blockIdx.x * blockDim.x + threadIdx.x;
    if (e < NE) {
        int p = atomicAdd(&g_cursor[dst[e]], 1);
        g_eid[p] = e;
    }
}

// ---------------- dual f32x2 GEMM v3: conflict-free B cols + cp.async pipeline --
// Thread (tx,ty) owns rows ty*4..+3, cols {tx*4..+3, tx*4+32..+35}.
__global__ void __launch_bounds__(128, 4) sgemm_dual(
    const float* __restrict__ A,
    const float* __restrict__ Bl, const float* __restrict__ bil, float* __restrict__ Cl,
    const float* __restrict__ Br, const float* __restrict__ bir, float* __restrict__ Cr,
    int M, int N, int K)
{
    __shared__ float sA [2][16][64];
    __shared__ float sBl[2][16][64];
    __shared__ float sBr[2][16][64];
    const int tid = threadIdx.x;
    const int bm = blockIdx.y * 64, bn = blockIdx.x * 64;
    const int tx = tid & 7, ty = tid >> 3;
    const int ar = tid >> 1, ak = (tid & 1) * 8;       // A stage: row, k-offset
    const int brow = tid >> 4, bcc = (tid & 15) * 4;   // B stage: 2 chunks/thread

    ull accl[4][4], accr[4][4];
    #pragma unroll
    for (int i = 0; i < 4; i++)
        #pragma unroll
        for (int j = 0; j < 4; j++) { accl[i][j] = 0ull; accr[i][j] = 0ull; }

    // B chunk staging: thread copies rows {brow, brow+8} at col chunk bcc (16B each)
    auto stageB = [&](int k0, int b) {
        unsigned sl = (unsigned)__cvta_generic_to_shared(&sBl[b][brow][bcc]);
        unsigned sr = (unsigned)__cvta_generic_to_shared(&sBr[b][brow][bcc]);
        cpa16(sl,                 &Bl[(size_t)(k0 + brow) * N + bn + bcc]);
        cpa16(sl + 8 * 64 * 4,    &Bl[(size_t)(k0 + brow + 8) * N + bn + bcc]);
        cpa16(sr,                 &Br[(size_t)(k0 + brow) * N + bn + bcc]);
        cpa16(sr + 8 * 64 * 4,    &Br[(size_t)(k0 + brow + 8) * N + bn + bcc]);
    };
    auto stsA = [&](int b, float4 a0, float4 a1) {
        sA[b][ak + 0][ar] = a0.x; sA[b][ak + 1][ar] = a0.y;
        sA[b][ak + 2][ar] = a0.z; sA[b][ak + 3][ar] = a0.w;
        sA[b][ak + 4][ar] = a1.x; sA[b][ak + 5][ar] = a1.y;
        sA[b][ak + 6][ar] = a1.z; sA[b][ak + 7][ar] = a1.w;
    };

    // prologue: tile 0
    {
        float4 a0 = *(const float4*)&A[(size_t)(bm + ar) * K + ak];
        float4 a1 = *(const float4*)&A[(size_t)(bm + ar) * K + ak + 4];
        stageB(0, 0);
        CPA_COMMIT();
        stsA(0, a0, a1);
        CPA_WAIT0();
        __syncthreads();
    }

    const int NT = K / 16;
    for (int t = 0; t < NT; t++) {
        const int buf = t & 1;
        float4 na0, na1;
        const bool more = (t + 1 < NT);
        if (more) {
            int k0n = (t + 1) * 16;
            na0 = *(const float4*)&A[(size_t)(bm + ar) * K + k0n + ak];
            na1 = *(const float4*)&A[(size_t)(bm + ar) * K + k0n + ak + 4];
            stageB(k0n, buf ^ 1);
            CPA_COMMIT();
        }
        #pragma unroll
        for (int k = 0; k < 16; k++) {
            float4 av4 = *(float4*)&sA[buf][k][ty * 4];
            f4u bl01, bl23, br01, br23;
            bl01.f = *(float4*)&sBl[buf][k][tx * 4];
            bl23.f = *(float4*)&sBl[buf][k][tx * 4 + 32];
            br01.f = *(float4*)&sBr[buf][k][tx * 4];
            br23.f = *(float4*)&sBr[buf][k][tx * 4 + 32];
            ull av[4] = {pk2(av4.x, av4.x), pk2(av4.y, av4.y),
                         pk2(av4.z, av4.z), pk2(av4.w, av4.w)};
            ull blv[4] = {bl01.u[0], bl01.u[1], bl23.u[0], bl23.u[1]};
            ull brv[4] = {br01.u[0], br01.u[1], br23.u[0], br23.u[1]};
            #pragma unroll
            for (int i = 0; i < 4; i++)
                #pragma unroll
                for (int j = 0; j < 4; j++) {
                    accl[i][j] = fma2(av[i], blv[j], accl[i][j]);
                    accr[i][j] = fma2(av[i], brv[j], accr[i][j]);
                }
        }
        if (more) {
            stsA(buf ^ 1, na0, na1);
            CPA_WAIT0();
            __syncthreads();
        }
    }

    // epilogue: cols tx*4 and tx*4+32
    float bsl[8], bsr[8];
    #pragma unroll
    for (int j = 0; j < 4; j++) {
        bsl[j]     = bil[bn + tx * 4 + j];
        bsl[4 + j] = bil[bn + tx * 4 + 32 + j];
        bsr[j]     = bir[bn + tx * 4 + j];
        bsr[4 + j] = bir[bn + tx * 4 + 32 + j];
    }
    #pragma unroll
    for (int i = 0; i < 4; i++) {
        float ol[8], orr[8];
        #pragma unroll
        for (int j = 0; j < 4; j++) {
            upk2(accl[i][j], ol[2 * j], ol[2 * j + 1]);
            upk2(accr[i][j], orr[2 * j], orr[2 * j + 1]);
        }
        #pragma unroll
        for (int j = 0; j < 8; j++) { ol[j] += bsl[j]; orr[j] += bsr[j]; }
        size_t row = (size_t)(bm + ty * 4 + i);
        *(float4*)&Cl[row * N + bn + tx * 4]      = make_float4(ol[0], ol[1], ol[2], ol[3]);
        *(float4*)&Cl[row * N + bn + tx * 4 + 32] = make_float4(ol[4], ol[5], ol[6], ol[7]);
        *(float4*)&Cr[row * N + bn + tx * 4]      = make_float4(orr[0], orr[1], orr[2], orr[3]);
        *(float4*)&Cr[row * N + bn + tx * 4 + 32] = make_float4(orr[4], orr[5], orr[6], orr[7]);
    }
}

// ---------------- single GEMM v3 (gate layer, relu): same pipeline ----------------
__global__ void __launch_bounds__(128, 4) sgemm2(
    const float* __restrict__ A, const float* __restrict__ B,
    const float* __restrict__ bias, float* __restrict__ C,
    int M, int N, int K, int doRelu)
{
    __shared__ float sA[2][16][64];
    __shared__ float sB[2][16][64];
    const int tid = threadIdx.x;
    const int bm = blockIdx.y * 64, bn = blockIdx.x * 64;
    const int tx = tid & 7, ty = tid >> 3;
    const int ar = tid >> 1, ak = (tid & 1) * 8;
    const int brow = tid >> 4, bcc = (tid & 15) * 4;

    ull acc[4][4];
    #pragma unroll
    for (int i = 0; i < 4; i++)
        #pragma unroll
        for (int j = 0; j < 4; j++) acc[i][j] = 0ull;

    auto stageB = [&](int k0, int b) {
        unsigned s = (unsigned)__cvta_generic_to_shared(&sB[b][brow][bcc]);
        cpa16(s,              &B[(size_t)(k0 + brow) * N + bn + bcc]);
        cpa16(s + 8 * 64 * 4, &B[(size_t)(k0 + brow + 8) * N + bn + bcc]);
    };
    auto stsA = [&](int b, float4 a0, float4 a1) {
        sA[b][ak + 0][ar] = a0.x; sA[b][ak + 1][ar] = a0.y;
        sA[b][ak + 2][ar] = a0.z; sA[b][ak + 3][ar] = a0.w;
        sA[b][ak + 4][ar] = a1.x; sA[b][ak + 5][ar] = a1.y;
        sA[b][ak + 6][ar] = a1.z; sA[b][ak + 7][ar] = a1.w;
    };

    {
        float4 a0 = *(const float4*)&A[(size_t)(bm + ar) * K + ak];
        float4 a1 = *(const float4*)&A[(size_t)(bm + ar) * K + ak + 4];
        stageB(0, 0);
        CPA_COMMIT();
        stsA(0, a0, a1);
        CPA_WAIT0();
        __syncthreads();
    }

    const int NT = K / 16;
    for (int t = 0; t < NT; t++) {
        const int buf = t & 1;
        float4 na0, na1;
        const bool more = (t + 1 < NT);
        if (more) {
            int k0n = (t + 1) * 16;
            na0 = *(const float4*)&A[(size_t)(bm + ar) * K + k0n + ak];
            na1 = *(const float4*)&A[(size_t)(bm + ar) * K + k0n + ak + 4];
            stageB(k0n, buf ^ 1);
            CPA_COMMIT();
        }
        #pragma unroll
        for (int k = 0; k < 16; k++) {
            float4 av4 = *(float4*)&sA[buf][k][ty * 4];
            f4u b01, b23;
            b01.f = *(float4*)&sB[buf][k][tx * 4];
            b23.f = *(float4*)&sB[buf][k][tx * 4 + 32];
            ull av[4] = {pk2(av4.x, av4.x), pk2(av4.y, av4.y),
                         pk2(av4.z, av4.z), pk2(av4.w, av4.w)};
            ull bv[4] = {b01.u[0], b01.u[1], b23.u[0], b23.u[1]};
            #pragma unroll
            for (int i = 0; i < 4; i++)
                #pragma unroll
                for (int j = 0; j < 4; j++)
                    acc[i][j] = fma2(av[i], bv[j], acc[i][j]);
        }
        if (more) {
            stsA(buf ^ 1, na0, na1);
            CPA_WAIT0();
            __syncthreads();
        }
    }

    float bs[8];
    #pragma unroll
    for (int j = 0; j < 4; j++) {
        bs[j]     = bias[bn + tx * 4 + j];
        bs[4 + j] = bias[bn + tx * 4 + 32 + j];
    }
    #pragma unroll
    for (int i = 0; i < 4; i++) {
        float o[8];
        #pragma unroll
        for (int j = 0; j < 4; j++) upk2(acc[i][j], o[2 * j], o[2 * j + 1]);
        #pragma unroll
        for (int j = 0; j < 8; j++) {
            o[j] += bs[j];
            if (doRelu) o[j] = fmaxf(o[j], 0.f);
        }
        size_t row = (size_t)(bm + ty * 4 + i);
        *(float4*)&C[row * N + bn + tx * 4]      = make_float4(o[0], o[1], o[2], o[3]);
        *(float4*)&C[row * N + bn + tx * 4 + 32] = make_float4(o[4], o[5], o[6], o[7]);
    }
}

// ---------------- edge weights v6 (champion, frozen) ----------------
template<int HC, int H>
__global__ void __launch_bounds__(256) edge_logits6(
    const float* __restrict__ xl, const float* __restrict__ xr,
    const float* __restrict__ We, const float* __restrict__ att,
    const float* __restrict__ ea, const int* __restrict__ src,
    const int* __restrict__ dst, float* __restrict__ wout)
{
    constexpr int CPT = HC / 32;
    constexpr int CP  = CPT / 2;
    constexpr int EPB = 128;
    const int tid = threadIdx.x;
    const int wid = tid >> 5, lane = tid & 31;
    const long ebase = (long)blockIdx.x * EPB;

    __shared__ float sWe[32][HC];
    __shared__ float sea_t[32][132];
    __shared__ int ssrc[EPB], sdst[EPB];

    for (int i = tid * 4; i < 32 * HC; i += 256 * 4)
        *(float4*)&sWe[0][i] = *(const float4*)&We[i];
    {
        const float4* eap = (const float4*)(ea + ebase * 32);
        #pragma unroll
        for (int it = 0; it < 4; it++) {
            int i = tid + it * 256;
            float4 v = eap[i];
            int e = i >> 3, k4 = (i & 7) * 4;
            sea_t[k4 + 0][e] = v.x;
            sea_t[k4 + 1][e] = v.y;
            sea_t[k4 + 2][e] = v.z;
            sea_t[k4 + 3][e] = v.w;
        }
    }
    if (tid < EPB) {
        ssrc[tid] = src[ebase + tid];
        sdst[tid] = dst[ebase + tid];
    }
    float atr[CPT];
    #pragma unroll
    for (int i = 0; i < CPT; i++) atr[i] = att[lane * CPT + i];
    __syncthreads();

    #pragma unroll
    for (int eb = 0; eb < 2; eb++) {
        const int e0 = wid * 16 + eb * 8;
        ull acc[8][CP];
        #pragma unroll
        for (int e = 0; e < 8; e++)
            #pragma unroll
            for (int p = 0; p < CP; p++) acc[e][p] = 0ull;

        #pragma unroll 4
        for (int k = 0; k < 32; k++) {
            ull wv[CP];
            if (CPT == 4) {
                f4u w4; w4.f = *(float4*)&sWe[k][lane * 4];
                wv[0] = w4.u[0]; if (CP > 1) wv[1] = w4.u[1];
            } else {
                f2u w2; w2.f = *(float2*)&sWe[k][lane * 2];
                wv[0] = w2.u;
            }
            float4 ev0 = *(float4*)&sea_t[k][e0];
            float4 ev1 = *(float4*)&sea_t[k][e0 + 4];
            ull d[8];
            d[0] = pk2(ev0.x, ev0.x); d[1] = pk2(ev0.y, ev0.y);
            d[2] = pk2(ev0.z, ev0.z); d[3] = pk2(ev0.w, ev0.w);
            d[4] = pk2(ev1.x, ev1.x); d[5] = pk2(ev1.y, ev1.y);
            d[6] = pk2(ev1.z, ev1.z); d[7] = pk2(ev1.w, ev1.w);
            #pragma unroll
            for (int e = 0; e < 8; e++)
                #pragma unroll
                for (int p = 0; p < CP; p++)
                    acc[e][p] = fma2(d[e], wv[p], acc[e][p]);
        }

        #pragma unroll
        for (int e = 0; e < 8; e++) {
            const size_t sn = (size_t)ssrc[e0 + e];
            const size_t dn = (size_t)sdst[e0 + e];
            float s[CPT];
            if (CPT == 4) {
                float4 xa = *(const float4*)&xl[sn * HC + lane * 4];
                float4 xb = *(const float4*)&xr[dn * HC + lane * 4];
                float e01lo, e01hi, e23lo, e23hi;
                upk2(acc[e][0], e01lo, e01hi);
                upk2(acc[e][CP > 1 ? 1 : 0], e23lo, e23hi);
                s[0] = xa.x + xb.x + e01lo;
                s[1] = xa.y + xb.y + e01hi;
                s[2] = xa.z + xb.z + e23lo;
                s[3] = xa.w + xb.w + e23hi;
            } else {
                float2 xa = *(const float2*)&xl[sn * HC + lane * 2];
                float2 xb = *(const float2*)&xr[dn * HC + lane * 2];
                float elo, ehi;
                upk2(acc[e][0], elo, ehi);
                s[0] = xa.x + xb.x + elo;
                s[1] = xa.y + xb.y + ehi;
            }
            float p = 0.f;
            #pragma unroll
            for (int i = 0; i < CPT; i++) {
                float v = fmaxf(s[i], 0.f) + 0.2f * fminf(s[i], 0.f);
                p += v * atr[i];
            }
            const long ge = ebase + e0 + e;
            if (H == 2) {
                #pragma unroll
                for (int off = 8; off; off >>= 1)
                    p += __shfl_down_sync(0xffffffffu, p, off, 16);
                if ((lane & 15) == 0) wout[ge * 2 + (lane >> 4)] = __expf(p);
            } else {
                #pragma unroll
                for (int off = 16; off; off >>= 1)
                    p += __shfl_down_sync(0xffffffffu, p, off);
                if (lane == 0) wout[ge] = __expf(p);
            }
        }
    }
}

// ---------------- per-dst normalize + weighted aggregation ----------------
template<int HC, int H, bool RELU>
__global__ void __launch_bounds__(HC / 2) agg3(
    const float* __restrict__ xl, const float* __restrict__ wexp,
    const int* __restrict__ src, const float* __restrict__ bias,
    float* __restrict__ out)
{
    const int n = blockIdx.x, t = threadIdx.x;
    const int lane = t & 31, wid = t >> 5;
    __shared__ float s_w[H][64];
    __shared__ int s_srcn[64];
    __shared__ float s_den[H];
    const int r0 = g_rowptr[n], deg = g_rowptr[n + 1] - r0;
    const float2* xl2 = (const float2*)xl;
    const int HC2 = HC / 2;

    float accx = 0.f, accy = 0.f, dpart = 0.f;
    for (int b0 = 0; b0 < deg; b0 += 64) {
        int cnt = min(64, deg - b0);
        for (int i = lane; i < cnt; i += 32) {
            int e = g_eid[r0 + b0 + i];
            float w = wexp[(size_t)e * H + wid];
            s_w[wid][i] = w;
            dpart += w;
            if (wid == 0) s_srcn[i] = src[e];
        }
        __syncthreads();
        int i = 0;
        for (; i + 4 <= cnt; i += 4) {
            int n0 = s_srcn[i], n1 = s_srcn[i + 1], n2 = s_srcn[i + 2], n3 = s_srcn[i + 3];
            float w0 = s_w[wid][i], w1 = s_w[wid][i + 1], w2v = s_w[wid][i + 2], w3 = s_w[wid][i + 3];
            float2 v0 = xl2[(size_t)n0 * HC2 + t];
            float2 v1 = xl2[(size_t)n1 * HC2 + t];
            float2 v2 = xl2[(size_t)n2 * HC2 + t];
            float2 v3 = xl2[(size_t)n3 * HC2 + t];
            accx += w0 * v0.x + w1 * v1.x + w2v * v2.x + w3 * v3.x;
            accy += w0 * v0.y + w1 * v1.y + w2v * v2.y + w3 * v3.y;
        }
        for (; i < cnt; i++) {
            float w = s_w[wid][i];
            float2 v = xl2[(size_t)s_srcn[i] * HC2 + t];
            accx += w * v.x;
            accy += w * v.y;
        }
        __syncthreads();
    }
    #pragma unroll
    for (int off = 16; off; off >>= 1)
        dpart += __shfl_xor_sync(0xffffffffu, dpart, off);
    if (lane == 0) s_den[wid] = dpart;
    __syncthreads();
    float inv = 1.f / (s_den[wid] + 1e-16f);
    float ox = accx * inv + bias[2 * t];
    float oy = accy * inv + bias[2 * t + 1];
    if (RELU) { ox = fmaxf(ox, 0.f); oy = fmaxf(oy, 0.f); }
    *(float2*)&out[(size_t)n * HC + 2 * t] = make_float2(ox, oy);
}

// ---------------- gate ----------------
__global__ void k_gate2(const float* __restrict__ hid, const float* __restrict__ G2w,
                        const float* __restrict__ G2b)
{
    int wid = threadIdx.x >> 5, lane = threadIdx.x & 31;
    int n = blockIdx.x * 4 + wid;
    if (n >= NN) return;
    float v = 0.f;
    #pragma unroll
    for (int i = 0; i < 4; i++) {
        int c = lane + 32 * i;
        v += hid[(size_t)n * 128 + c] * G2w[c];
    }
    #pragma unroll
    for (int off = 16; off; off >>= 1) v += __shfl_xor_sync(0xffffffffu, v, off);
    if (lane == 0) g_gate[n] = __expf(v + G2b[0]);
}

// ---------------- block-per-graph pool + regressor ----------------
__global__ void k_poolout(const int* __restrict__ batch, const float* __restrict__ h3,
                          const float* __restrict__ Wreg, const float* __restrict__ breg,
                          float* __restrict__ out)
{
    const int b = blockIdx.x, c = threadIdx.x;   // 64 threads
    __shared__ int s_range[2];
    if (c < 2) {
        int key = b + c;
        int lo = 0, hi = NN;
        while (lo < hi) { int m = (lo + hi) >> 1; if (batch[m] < key) lo = m + 1; else hi = m; }
        s_range[c] = lo;
    }
    __syncthreads();
    int lo = s_range[0], hi = s_range[1];
    float acc = 0.f, den = 0.f;
    int n = lo;
    for (; n + 4 <= hi; n += 4) {
        float g0 = g_gate[n], g1 = g_gate[n + 1], g2 = g_gate[n + 2], g3 = g_gate[n + 3];
        float h0 = h3[(size_t)n * 64 + c];
        float h1 = h3[(size_t)(n + 1) * 64 + c];
        float h2 = h3[(size_t)(n + 2) * 64 + c];
        float hv3 = h3[(size_t)(n + 3) * 64 + c];
        acc += g0 * h0 + g1 * h1 + g2 * h2 + g3 * hv3;
        den += g0 + g1 + g2 + g3;
    }
    for (; n < hi; n++) {
        float g = g_gate[n];
        acc += g * h3[(size_t)n * 64 + c];
        den += g;
    }
    float v = acc / (den + 1e-16f) * Wreg[c];
    #pragma unroll
    for (int off = 16; off; off >>= 1) v += __shfl_xor_sync(0xffffffffu, v, off);
    __shared__ float sp[2];
    if ((c & 31) == 0) sp[c >> 5] = v;
    __syncthreads();
    if (c == 0) out[b] = sp[0] + sp[1] + breg[0];
}

// ---------------- launch ----------------
extern "C" void kernel_launch(void* const* d_in, const int* in_sizes, int n_in,
                              void* d_out, int out_size)
{
    const float* x     = (const float*)d_in[0];
    const float* eattr = (const float*)d_in[1];
    const int*   eidx  = (const int*)d_in[2];
    const int*   batch = (const int*)d_in[3];
    const float *W1l = (const float*)d_in[4],  *b1l = (const float*)d_in[5];
    const float *W1r = (const float*)d_in[6],  *b1r = (const float*)d_in[7];
    const float *W1e = (const float*)d_in[8],  *att1 = (const float*)d_in[9];
    const float *bias1 = (const float*)d_in[10];
    const float *W2l = (const float*)d_in[11], *b2l = (const float*)d_in[12];
    const float *W2r = (const float*)d_in[13], *b2r = (const float*)d_in[14];
    const float *W2e = (const float*)d_in[15], *att2 = (const float*)d_in[16];
    const float *bias2 = (const float*)d_in[17];
    const float *W3l = (const float*)d_in[18], *b3l = (const float*)d_in[19];
    const float *W3r = (const float*)d_in[20], *b3r = (const float*)d_in[21];
    const float *W3e = (const float*)d_in[22], *att3 = (const float*)d_in[23];
    const float *bias3 = (const float*)d_in[24];
    const float *G1w = (const float*)d_in[25], *G1b = (const float*)d_in[26];
    const float *G2w = (const float*)d_in[27], *G2b = (const float*)d_in[28];
    const float *Wreg = (const float*)d_in[29], *breg = (const float*)d_in[30];
    float* out = (float*)d_out;

    const int* src = eidx;
    const int* dst = eidx + NE;

    float *xl, *xr, *hbuf, *wexp;
    cudaGetSymbolAddress((void**)&xl, g_xl);
    cudaGetSymbolAddress((void**)&xr, g_xr);
    cudaGetSymbolAddress((void**)&hbuf, g_h);
    cudaGetSymbolAddress((void**)&wexp, g_w);

    dim3 g2(2, NN / 64), g1(1, NN / 64);

    // ordering note: app-kernel index 3 (sgemm_dual) is what ncu -s 5 profiles
    k_init<<<(NN + 255) / 256, 256>>>();                                          // 0
    k_count<<<(NE + 255) / 256, 256>>>(dst);                                      // 1
    k_scan<<<1, 1024>>>();                                                        // 2
    sgemm_dual<<<g2, 128>>>(x, W1l, b1l, xl, W1r, b1r, xr, NN, 128, 128);         // 3  <- profiled
    k_scatter<<<(NE + 255) / 256, 256>>>(dst);                                    // 4
    edge_logits6<128, 2><<<NE / 128, 256>>>(xl, xr, W1e, att1, eattr, src, dst, wexp); // 5
    agg3<128, 2, true><<<NN, 64>>>(xl, wexp, src, bias1, hbuf);                   // 6

    sgemm_dual<<<g2, 128>>>(hbuf, W2l, b2l, xl, W2r, b2r, xr, NN, 128, 128);      // 7
    edge_logits6<128, 2><<<NE / 128, 256>>>(xl, xr, W2e, att2, eattr, src, dst, wexp); // 8
    agg3<128, 2, true><<<NN, 64>>>(xl, wexp, src, bias2, hbuf);                   // 9

    sgemm_dual<<<g1, 128>>>(hbuf, W3l, b3l, xl, W3r, b3r, xr, NN, 64, 128);       // 10
    edge_logits6<64, 1><<<NE / 128, 256>>>(xl, xr, W3e, att3, eattr, src, dst, wexp);  // 11
    agg3<64, 1, false><<<NN, 32>>>(xl, wexp, src, bias3, hbuf);                   // 12

    sgemm2<<<g2, 128>>>(hbuf, G1w, G1b, xl, NN, 128, 64, 1);                      // 13
    k_gate2<<<NN / 4, 128>>>(xl, G2w, G2b);                                       // 14
    k_poolout<<<NBATCH, 64>>>(batch, hbuf, Wreg, breg, out);                      // 15
}

// round 17
// speedup vs baseline: 1.4386x; 1.4386x over previous
#include <cuda_runtime.h>

#define NN 40000
#define NE 640000
#define NBATCH 64

typedef unsigned long long ull;

// ---------------- f32x2 helpers ----------------
__device__ __forceinline__ ull pk2(float lo, float hi) {
    ull r; asm("mov.b64 %0, {%1,%2};" : "=l"(r) : "f"(lo), "f"(hi)); return r;
}
__device__ __forceinline__ void upk2(ull v, float& lo, float& hi) {
    asm("mov.b64 {%0,%1}, %2;" : "=f"(lo), "=f"(hi) : "l"(v));
}
__device__ __forceinline__ ull fma2(ull a, ull b, ull c) {
    ull d; asm("fma.rn.f32x2 %0, %1, %2, %3;" : "=l"(d) : "l"(a), "l"(b), "l"(c)); return d;
}
union f4u { float4 f; ull u[2]; };
union f2u { float2 f; ull u; };

// ---------------- scratch ----------------
__device__ float g_xl[NN * 128];
__device__ float g_xr[NN * 128];
__device__ float g_h [NN * 128];
__device__ float g_w  [NE * 2];       // exp(logit)
__device__ int   g_rowptr[NN + 1];
__device__ int   g_cursor[NN];
__device__ int   g_eid[NE];
__device__ float g_gate[NN];          // exp(gate logit)

// ---------------- CSR build ----------------
__global__ void k_init() {
    int i = blockIdx.x * blockDim.x + threadIdx.x;
    if (i < NN) g_cursor[i] = 0;
}
__global__ void k_count(const int* __restrict__ dst) {
    int e = blockIdx.x * blockDim.x + threadIdx.x;
    if (e < NE) atomicAdd(&g_cursor[dst[e]], 1);
}
__global__ void __launch_bounds__(1024) k_scan() {
    const int t = threadIdx.x;
    const int lane = t & 31, w = t >> 5;
    const int base = t * 40;
    const int n0 = min(base, NN), n1 = min(base + 40, NN);
    int sum = 0;
    for (int i = n0; i < n1; i++) sum += g_cursor[i];
    int v = sum;
    #pragma unroll
    for (int off = 1; off < 32; off <<= 1) {
        int u = __shfl_up_sync(0xffffffffu, v, off);
        if (lane >= off) v += u;
    }
    __shared__ int ws[32];
    if (lane == 31) ws[w] = v;
    __syncthreads();
    if (w == 0) {
        int x = ws[lane];
        #pragma unroll
        for (int off = 1; off < 32; off <<= 1) {
            int u = __shfl_up_sync(0xffffffffu, x, off);
            if (lane >= off) x += u;
        }
        ws[lane] = x;
    }
    __syncthreads();
    int excl = v - sum + (w > 0 ? ws[w - 1] : 0);
    if (t == 0) g_rowptr[0] = 0;
    int run = excl;
    for (int i = n0; i < n1; i++) {
        int c = g_cursor[i];
        g_cursor[i] = run;
        g_rowptr[i + 1] = run + c;
        run += c;
    }
}
__global__ void k_scatter(const int* __restrict__ dst) {
    int e = blockIdx.x * blockDim.x + threadIdx.x;
    if (e < NE) {
        int p = atomicAdd(&g_cursor[dst[e]], 1);
        g_eid[p] = e;
    }
}

// ---------------- dual f32x2 GEMM (R13 body + conflict-free B columns) ---------
// Thread (tx,ty) owns rows ty*4..+3, cols {tx*4..+3, tx*4+32..+35}:
// B reads at sB[k][tx*4] span floats 0..31 across the warp half -> banks 0..31,
// zero conflicts (was tx*8: 2-way conflict on every B LDS.128).
__global__ void __launch_bounds__(128, 4) sgemm_dual(
    const float* __restrict__ A,
    const float* __restrict__ Bl, const float* __restrict__ bil, float* __restrict__ Cl,
    const float* __restrict__ Br, const float* __restrict__ bir, float* __restrict__ Cr,
    int M, int N, int K)
{
    __shared__ float sA[16][64];
    __shared__ float sBl[16][64];
    __shared__ float sBr[16][64];
    const int tid = threadIdx.x;
    const int bm = blockIdx.y * 64, bn = blockIdx.x * 64;
    const int tx = tid & 7, ty = tid >> 3;
    const int ar = tid >> 1, ak = (tid & 1) * 8;
    const int br = tid >> 3, bc = (tid & 7) * 8;

    ull accl[4][4], accr[4][4];
    #pragma unroll
    for (int i = 0; i < 4; i++)
        #pragma unroll
        for (int j = 0; j < 4; j++) { accl[i][j] = 0ull; accr[i][j] = 0ull; }

    for (int k0 = 0; k0 < K; k0 += 16) {
        float4 a0 = *(const float4*)&A[(size_t)(bm + ar) * K + k0 + ak];
        float4 a1 = *(const float4*)&A[(size_t)(bm + ar) * K + k0 + ak + 4];
        sA[ak + 0][ar] = a0.x;
        sA[ak + 1][ar] = a0.y;
        sA[ak + 2][ar] = a0.z;
        sA[ak + 3][ar] = a0.w;
        sA[ak + 4][ar] = a1.x;
        sA[ak + 5][ar] = a1.y;
        sA[ak + 6][ar] = a1.z;
        sA[ak + 7][ar] = a1.w;
        *(float4*)&sBl[br][bc]     = *(const float4*)&Bl[(size_t)(k0 + br) * N + bn + bc];
        *(float4*)&sBl[br][bc + 4] = *(const float4*)&Bl[(size_t)(k0 + br) * N + bn + bc + 4];
        *(float4*)&sBr[br][bc]     = *(const float4*)&Br[(size_t)(k0 + br) * N + bn + bc];
        *(float4*)&sBr[br][bc + 4] = *(const float4*)&Br[(size_t)(k0 + br) * N + bn + bc + 4];
        __syncthreads();
        #pragma unroll
        for (int k = 0; k < 16; k++) {
            float4 av4 = *(float4*)&sA[k][ty * 4];
            f4u bl01, bl23, br01, br23;
            bl01.f = *(float4*)&sBl[k][tx * 4];
            bl23.f = *(float4*)&sBl[k][tx * 4 + 32];
            br01.f = *(float4*)&sBr[k][tx * 4];
            br23.f = *(float4*)&sBr[k][tx * 4 + 32];
            ull av[4] = {pk2(av4.x, av4.x), pk2(av4.y, av4.y),
                         pk2(av4.z, av4.z), pk2(av4.w, av4.w)};
            ull blv[4] = {bl01.u[0], bl01.u[1], bl23.u[0], bl23.u[1]};
            ull brv[4] = {br01.u[0], br01.u[1], br23.u[0], br23.u[1]};
            #pragma unroll
            for (int i = 0; i < 4; i++)
                #pragma unroll
                for (int j = 0; j < 4; j++) {
                    accl[i][j] = fma2(av[i], blv[j], accl[i][j]);
                    accr[i][j] = fma2(av[i], brv[j], accr[i][j]);
                }
        }
        __syncthreads();
    }
    float bsl[8], bsr[8];
    #pragma unroll
    for (int j = 0; j < 4; j++) {
        bsl[j]     = bil[bn + tx * 4 + j];
        bsl[4 + j] = bil[bn + tx * 4 + 32 + j];
        bsr[j]     = bir[bn + tx * 4 + j];
        bsr[4 + j] = bir[bn + tx * 4 + 32 + j];
    }
    #pragma unroll
    for (int i = 0; i < 4; i++) {
        float ol[8], orr[8];
        #pragma unroll
        for (int j = 0; j < 4; j++) {
            upk2(accl[i][j], ol[2 * j], ol[2 * j + 1]);
            upk2(accr[i][j], orr[2 * j], orr[2 * j + 1]);
        }
        #pragma unroll
        for (int j = 0; j < 8; j++) { ol[j] += bsl[j]; orr[j] += bsr[j]; }
        size_t row = (size_t)(bm + ty * 4 + i);
        *(float4*)&Cl[row * N + bn + tx * 4]      = make_float4(ol[0], ol[1], ol[2], ol[3]);
        *(float4*)&Cl[row * N + bn + tx * 4 + 32] = make_float4(ol[4], ol[5], ol[6], ol[7]);
        *(float4*)&Cr[row * N + bn + tx * 4]      = make_float4(orr[0], orr[1], orr[2], orr[3]);
        *(float4*)&Cr[row * N + bn + tx * 4 + 32] = make_float4(orr[4], orr[5], orr[6], orr[7]);
    }
}

// ---------------- single GEMM (gate layer, relu; conflict-free B columns) ------
__global__ void __launch_bounds__(128) sgemm2(
    const float* __restrict__ A, const float* __restrict__ B,
    const float* __restrict__ bias, float* __restrict__ C,
    int M, int N, int K, int doRelu)
{
    __shared__ float sA[16][64];
    __shared__ float sB[16][64];
    const int tid = threadIdx.x;
    const int bm = blockIdx.y * 64, bn = blockIdx.x * 64;
    const int tx = tid & 7, ty = tid >> 3;
    const int ar = tid >> 1, ak = (tid & 1) * 8;
    const int br = tid >> 3, bc = (tid & 7) * 8;

    ull acc[4][4];
    #pragma unroll
    for (int i = 0; i < 4; i++)
        #pragma unroll
        for (int j = 0; j < 4; j++) acc[i][j] = 0ull;

    for (int k0 = 0; k0 < K; k0 += 16) {
        float4 a0 = *(const float4*)&A[(size_t)(bm + ar) * K + k0 + ak];
        float4 a1 = *(const float4*)&A[(size_t)(bm + ar) * K + k0 + ak + 4];
        sA[ak + 0][ar] = a0.x;
        sA[ak + 1][ar] = a0.y;
        sA[ak + 2][ar] = a0.z;
        sA[ak + 3][ar] = a0.w;
        sA[ak + 4][ar] = a1.x;
        sA[ak + 5][ar] = a1.y;
        sA[ak + 6][ar] = a1.z;
        sA[ak + 7][ar] = a1.w;
        *(float4*)&sB[br][bc]     = *(const float4*)&B[(size_t)(k0 + br) * N + bn + bc];
        *(float4*)&sB[br][bc + 4] = *(const float4*)&B[(size_t)(k0 + br) * N + bn + bc + 4];
        __syncthreads();
        #pragma unroll
        for (int k = 0; k < 16; k++) {
            float4 av4 = *(float4*)&sA[k][ty * 4];
            f4u b01, b23;
            b01.f = *(float4*)&sB[k][tx * 4];
            b23.f = *(float4*)&sB[k][tx * 4 + 32];
            ull av[4] = {pk2(av4.x, av4.x), pk2(av4.y, av4.y),
                         pk2(av4.z, av4.z), pk2(av4.w, av4.w)};
            ull bv[4] = {b01.u[0], b01.u[1], b23.u[0], b23.u[1]};
            #pragma unroll
            for (int i = 0; i < 4; i++)
                #pragma unroll
                for (int j = 0; j < 4; j++)
                    acc[i][j] = fma2(av[i], bv[j], acc[i][j]);
        }
        __syncthreads();
    }
    float bs[8];
    #pragma unroll
    for (int j = 0; j < 4; j++) {
        bs[j]     = bias[bn + tx * 4 + j];
        bs[4 + j] = bias[bn + tx * 4 + 32 + j];
    }
    #pragma unroll
    for (int i = 0; i < 4; i++) {
        float o[8];
        #pragma unroll
        for (int j = 0; j < 4; j++) upk2(acc[i][j], o[2 * j], o[2 * j + 1]);
        #pragma unroll
        for (int j = 0; j < 8; j++) {
            o[j] += bs[j];
            if (doRelu) o[j] = fmaxf(o[j], 0.f);
        }
        size_t row = (size_t)(bm + ty * 4 + i);
        *(float4*)&C[row * N + bn + tx * 4]      = make_float4(o[0], o[1], o[2], o[3]);
        *(float4*)&C[row * N + bn + tx * 4 + 32] = make_float4(o[4], o[5], o[6], o[7]);
    }
}

// ---------------- edge weights v6 (champion, frozen) ----------------
template<int HC, int H>
__global__ void __launch_bounds__(256) edge_logits6(
    const float* __restrict__ xl, const float* __restrict__ xr,
    const float* __restrict__ We, const float* __restrict__ att,
    const float* __restrict__ ea, const int* __restrict__ src,
    const int* __restrict__ dst, float* __restrict__ wout)
{
    constexpr int CPT = HC / 32;
    constexpr int CP  = CPT / 2;
    constexpr int EPB = 128;
    const int tid = threadIdx.x;
    const int wid = tid >> 5, lane = tid & 31;
    const long ebase = (long)blockIdx.x * EPB;

    __shared__ float sWe[32][HC];
    __shared__ float sea_t[32][132];
    __shared__ int ssrc[EPB], sdst[EPB];

    for (int i = tid * 4; i < 32 * HC; i += 256 * 4)
        *(float4*)&sWe[0][i] = *(const float4*)&We[i];
    {
        const float4* eap = (const float4*)(ea + ebase * 32);
        #pragma unroll
        for (int it = 0; it < 4; it++) {
            int i = tid + it * 256;
            float4 v = eap[i];
            int e = i >> 3, k4 = (i & 7) * 4;
            sea_t[k4 + 0][e] = v.x;
            sea_t[k4 + 1][e] = v.y;
            sea_t[k4 + 2][e] = v.z;
            sea_t[k4 + 3][e] = v.w;
        }
    }
    if (tid < EPB) {
        ssrc[tid] = src[ebase + tid];
        sdst[tid] = dst[ebase + tid];
    }
    float atr[CPT];
    #pragma unroll
    for (int i = 0; i < CPT; i++) atr[i] = att[lane * CPT + i];
    __syncthreads();

    #pragma unroll
    for (int eb = 0; eb < 2; eb++) {
        const int e0 = wid * 16 + eb * 8;
        ull acc[8][CP];
        #pragma unroll
        for (int e = 0; e < 8; e++)
            #pragma unroll
            for (int p = 0; p < CP; p++) acc[e][p] = 0ull;

        #pragma unroll 4
        for (int k = 0; k < 32; k++) {
            ull wv[CP];
            if (CPT == 4) {
                f4u w4; w4.f = *(float4*)&sWe[k][lane * 4];
                wv[0] = w4.u[0]; if (CP > 1) wv[1] = w4.u[1];
            } else {
                f2u w2; w2.f = *(float2*)&sWe[k][lane * 2];
                wv[0] = w2.u;
            }
            float4 ev0 = *(float4*)&sea_t[k][e0];
            float4 ev1 = *(float4*)&sea_t[k][e0 + 4];
            ull d[8];
            d[0] = pk2(ev0.x, ev0.x); d[1] = pk2(ev0.y, ev0.y);
            d[2] = pk2(ev0.z, ev0.z); d[3] = pk2(ev0.w, ev0.w);
            d[4] = pk2(ev1.x, ev1.x); d[5] = pk2(ev1.y, ev1.y);
            d[6] = pk2(ev1.z, ev1.z); d[7] = pk2(ev1.w, ev1.w);
            #pragma unroll
            for (int e = 0; e < 8; e++)
                #pragma unroll
                for (int p = 0; p < CP; p++)
                    acc[e][p] = fma2(d[e], wv[p], acc[e][p]);
        }

        #pragma unroll
        for (int e = 0; e < 8; e++) {
            const size_t sn = (size_t)ssrc[e0 + e];
            const size_t dn = (size_t)sdst[e0 + e];
            float s[CPT];
            if (CPT == 4) {
                float4 xa = *(const float4*)&xl[sn * HC + lane * 4];
                float4 xb = *(const float4*)&xr[dn * HC + lane * 4];
                float e01lo, e01hi, e23lo, e23hi;
                upk2(acc[e][0], e01lo, e01hi);
                upk2(acc[e][CP > 1 ? 1 : 0], e23lo, e23hi);
                s[0] = xa.x + xb.x + e01lo;
                s[1] = xa.y + xb.y + e01hi;
                s[2] = xa.z + xb.z + e23lo;
                s[3] = xa.w + xb.w + e23hi;
            } else {
                float2 xa = *(const float2*)&xl[sn * HC + lane * 2];
                float2 xb = *(const float2*)&xr[dn * HC + lane * 2];
                float elo, ehi;
                upk2(acc[e][0], elo, ehi);
                s[0] = xa.x + xb.x + elo;
                s[1] = xa.y + xb.y + ehi;
            }
            float p = 0.f;
            #pragma unroll
            for (int i = 0; i < CPT; i++) {
                float v = fmaxf(s[i], 0.f) + 0.2f * fminf(s[i], 0.f);
                p += v * atr[i];
            }
            const long ge = ebase + e0 + e;
            if (H == 2) {
                #pragma unroll
                for (int off = 8; off; off >>= 1)
                    p += __shfl_down_sync(0xffffffffu, p, off, 16);
                if ((lane & 15) == 0) wout[ge * 2 + (lane >> 4)] = __expf(p);
            } else {
                #pragma unroll
                for (int off = 16; off; off >>= 1)
                    p += __shfl_down_sync(0xffffffffu, p, off);
                if (lane == 0) wout[ge] = __expf(p);
            }
        }
    }
}

// ---------------- per-dst normalize + weighted aggregation ----------------
template<int HC, int H, bool RELU>
__global__ void __launch_bounds__(HC / 2) agg3(
    const float* __restrict__ xl, const float* __restrict__ wexp,
    const int* __restrict__ src, const float* __restrict__ bias,
    float* __restrict__ out)
{
    const int n = blockIdx.x, t = threadIdx.x;
    const int lane = t & 31, wid = t >> 5;
    __shared__ float s_w[H][64];
    __shared__ int s_srcn[64];
    __shared__ float s_den[H];
    const int r0 = g_rowptr[n], deg = g_rowptr[n + 1] - r0;
    const float2* xl2 = (const float2*)xl;
    const int HC2 = HC / 2;

    float accx = 0.f, accy = 0.f, dpart = 0.f;
    for (int b0 = 0; b0 < deg; b0 += 64) {
        int cnt = min(64, deg - b0);
        for (int i = lane; i < cnt; i += 32) {
            int e = g_eid[r0 + b0 + i];
            float w = wexp[(size_t)e * H + wid];
            s_w[wid][i] = w;
            dpart += w;
            if (wid == 0) s_srcn[i] = src[e];
        }
        __syncthreads();
        int i = 0;
        for (; i + 4 <= cnt; i += 4) {
            int n0 = s_srcn[i], n1 = s_srcn[i + 1], n2 = s_srcn[i + 2], n3 = s_srcn[i + 3];
            float w0 = s_w[wid][i], w1 = s_w[wid][i + 1], w2v = s_w[wid][i + 2], w3 = s_w[wid][i + 3];
            float2 v0 = xl2[(size_t)n0 * HC2 + t];
            float2 v1 = xl2[(size_t)n1 * HC2 + t];
            float2 v2 = xl2[(size_t)n2 * HC2 + t];
            float2 v3 = xl2[(size_t)n3 * HC2 + t];
            accx += w0 * v0.x + w1 * v1.x + w2v * v2.x + w3 * v3.x;
            accy += w0 * v0.y + w1 * v1.y + w2v * v2.y + w3 * v3.y;
        }
        for (; i < cnt; i++) {
            float w = s_w[wid][i];
            float2 v = xl2[(size_t)s_srcn[i] * HC2 + t];
            accx += w * v.x;
            accy += w * v.y;
        }
        __syncthreads();
    }
    #pragma unroll
    for (int off = 16; off; off >>= 1)
        dpart += __shfl_xor_sync(0xffffffffu, dpart, off);
    if (lane == 0) s_den[wid] = dpart;
    __syncthreads();
    float inv = 1.f / (s_den[wid] + 1e-16f);
    float ox = accx * inv + bias[2 * t];
    float oy = accy * inv + bias[2 * t + 1];
    if (RELU) { ox = fmaxf(ox, 0.f); oy = fmaxf(oy, 0.f); }
    *(float2*)&out[(size_t)n * HC + 2 * t] = make_float2(ox, oy);
}

// ---------------- gate ----------------
__global__ void k_gate2(const float* __restrict__ hid, const float* __restrict__ G2w,
                        const float* __restrict__ G2b)
{
    int wid = threadIdx.x >> 5, lane = threadIdx.x & 31;
    int n = blockIdx.x * 4 + wid;
    if (n >= NN) return;
    float v = 0.f;
    #pragma unroll
    for (int i = 0; i < 4; i++) {
        int c = lane + 32 * i;
        v += hid[(size_t)n * 128 + c] * G2w[c];
    }
    #pragma unroll
    for (int off = 16; off; off >>= 1) v += __shfl_xor_sync(0xffffffffu, v, off);
    if (lane == 0) g_gate[n] = __expf(v + G2b[0]);
}

// ---------------- block-per-graph pool + regressor ----------------
__global__ void k_poolout(const int* __restrict__ batch, const float* __restrict__ h3,
                          const float* __restrict__ Wreg, const float* __restrict__ breg,
                          float* __restrict__ out)
{
    const int b = blockIdx.x, c = threadIdx.x;   // 64 threads
    __shared__ int s_range[2];
    if (c < 2) {
        int key = b + c;
        int lo = 0, hi = NN;
        while (lo < hi) { int m = (lo + hi) >> 1; if (batch[m] < key) lo = m + 1; else hi = m; }
        s_range[c] = lo;
    }
    __syncthreads();
    int lo = s_range[0], hi = s_range[1];
    float acc = 0.f, den = 0.f;
    int n = lo;
    for (; n + 4 <= hi; n += 4) {
        float g0 = g_gate[n], g1 = g_gate[n + 1], g2 = g_gate[n + 2], g3 = g_gate[n + 3];
        float h0 = h3[(size_t)n * 64 + c];
        float h1 = h3[(size_t)(n + 1) * 64 + c];
        float h2 = h3[(size_t)(n + 2) * 64 + c];
        float hv3 = h3[(size_t)(n + 3) * 64 + c];
        acc += g0 * h0 + g1 * h1 + g2 * h2 + g3 * hv3;
        den += g0 + g1 + g2 + g3;
    }
    for (; n < hi; n++) {
        float g = g_gate[n];
        acc += g * h3[(size_t)n * 64 + c];
        den += g;
    }
    float v = acc / (den + 1e-16f) * Wreg[c];
    #pragma unroll
    for (int off = 16; off; off >>= 1) v += __shfl_xor_sync(0xffffffffu, v, off);
    __shared__ float sp[2];
    if ((c & 31) == 0) sp[c >> 5] = v;
    __syncthreads();
    if (c == 0) out[b] = sp[0] + sp[1] + breg[0];
}

// ---------------- launch ----------------
extern "C" void kernel_launch(void* const* d_in, const int* in_sizes, int n_in,
                              void* d_out, int out_size)
{
    const float* x     = (const float*)d_in[0];
    const float* eattr = (const float*)d_in[1];
    const int*   eidx  = (const int*)d_in[2];
    const int*   batch = (const int*)d_in[3];
    const float *W1l = (const float*)d_in[4],  *b1l = (const float*)d_in[5];
    const float *W1r = (const float*)d_in[6],  *b1r = (const float*)d_in[7];
    const float *W1e = (const float*)d_in[8],  *att1 = (const float*)d_in[9];
    const float *bias1 = (const float*)d_in[10];
    const float *W2l = (const float*)d_in[11], *b2l = (const float*)d_in[12];
    const float *W2r = (const float*)d_in[13], *b2r = (const float*)d_in[14];
    const float *W2e = (const float*)d_in[15], *att2 = (const float*)d_in[16];
    const float *bias2 = (const float*)d_in[17];
    const float *W3l = (const float*)d_in[18], *b3l = (const float*)d_in[19];
    const float *W3r = (const float*)d_in[20], *b3r = (const float*)d_in[21];
    const float *W3e = (const float*)d_in[22], *att3 = (const float*)d_in[23];
    const float *bias3 = (const float*)d_in[24];
    const float *G1w = (const float*)d_in[25], *G1b = (const float*)d_in[26];
    const float *G2w = (const float*)d_in[27], *G2b = (const float*)d_in[28];
    const float *Wreg = (const float*)d_in[29], *breg = (const float*)d_in[30];
    float* out = (float*)d_out;

    const int* src = eidx;
    const int* dst = eidx + NE;

    float *xl, *xr, *hbuf, *wexp;
    cudaGetSymbolAddress((void**)&xl, g_xl);
    cudaGetSymbolAddress((void**)&xr, g_xr);
    cudaGetSymbolAddress((void**)&hbuf, g_h);
    cudaGetSymbolAddress((void**)&wexp, g_w);

    dim3 g2(2, NN / 64), g1(1, NN / 64);

    // ordering note: app-kernel index 3 (sgemm_dual) is what ncu -s 5 profiles
    k_init<<<(NN + 255) / 256, 256>>>();                                          // 0
    k_count<<<(NE + 255) / 256, 256>>>(dst);                                      // 1
    k_scan<<<1, 1024>>>();                                                        // 2
    sgemm_dual<<<g2, 128>>>(x, W1l, b1l, xl, W1r, b1r, xr, NN, 128, 128);         // 3  <- profiled
    k_scatter<<<(NE + 255) / 256, 256>>>(dst);                                    // 4
    edge_logits6<128, 2><<<NE / 128, 256>>>(xl, xr, W1e, att1, eattr, src, dst, wexp); // 5
    agg3<128, 2, true><<<NN, 64>>>(xl, wexp, src, bias1, hbuf);                   // 6

    sgemm_dual<<<g2, 128>>>(hbuf, W2l, b2l, xl, W2r, b2r, xr, NN, 128, 128);      // 7
    edge_logits6<128, 2><<<NE / 128, 256>>>(xl, xr, W2e, att2, eattr, src, dst, wexp); // 8
    agg3<128, 2, true><<<NN, 64>>>(xl, wexp, src, bias2, hbuf);                   // 9

    sgemm_dual<<<g1, 128>>>(hbuf, W3l, b3l, xl, W3r, b3r, xr, NN, 64, 128);       // 10
    edge_logits6<64, 1><<<NE / 128, 256>>>(xl, xr, W3e, att3, eattr, src, dst, wexp);  // 11
    agg3<64, 1, false><<<NN, 32>>>(xl, wexp, src, bias3, hbuf);                   // 12

    sgemm2<<<g2, 128>>>(hbuf, G1w, G1b, xl, NN, 128, 64, 1);                      // 13
    k_gate2<<<NN / 4, 128>>>(xl, G2w, G2b);                                       // 14
    k_poolout<<<NBATCH, 64>>>(batch, hbuf, Wreg, breg, out);                      // 15
}